// round 4
// baseline (speedup 1.0000x reference)
#include <cuda_runtime.h>
#include <cstdint>

#define T_  256
#define B_  64
#define H_  768
#define D_  1536
#define L_  3
#define G_  3072      // 4*H
#define TB_ 16384     // T*B

#define NCTA_DIR 48
#define WS_STRIDE 772          // 768 + 4 pad (words)
#define AS_STRIDE 36           // 32 + 4 pad (words)
#define SMEM_WORDS (64 * WS_STRIDE + 2 * 64 * AS_STRIDE)
#define SMEM_BYTES (SMEM_WORDS * 4)

// ---------------- scratch (__device__ globals: allocation-free rule) ----------------
__device__ __align__(256) float g_xg[2][TB_ * G_];       // per-dir input projections
__device__ __align__(256) float g_io[2][TB_ * 2 * H_];   // layer ping-pong buffers
__device__ __align__(256) float g_h[2][2][B_ * H_];      // [parity][dir] hidden state
__device__ int g_bar[2];
__device__ int g_gen[2];

// ---------------- tf32 helpers ----------------
__device__ __forceinline__ uint32_t f2tf32(float x) {
    uint32_t u;
    asm("cvt.rna.tf32.f32 %0, %1;" : "=r"(u) : "f"(x));
    return u;
}

__device__ __forceinline__ void mma_tf32(float c[4], const uint32_t a[4], const uint32_t b[2]) {
    asm volatile(
        "mma.sync.aligned.m16n8k8.row.col.f32.tf32.tf32.f32 "
        "{%0,%1,%2,%3}, {%4,%5,%6,%7}, {%8,%9}, {%0,%1,%2,%3};\n"
        : "+f"(c[0]), "+f"(c[1]), "+f"(c[2]), "+f"(c[3])
        : "r"(a[0]), "r"(a[1]), "r"(a[2]), "r"(a[3]), "r"(b[0]), "r"(b[1]));
}

__device__ __forceinline__ float sigmoidf_(float x) {
    return 1.0f / (1.0f + __expf(-x));
}

// =====================================================================
// xg GEMM: xg[m,n] = sum_k A[m,k] * W[n,k] + b_ih[n] + b_hh[n]
// M=TB_, N=G_, K=D_. BM=128,BN=128,BK=16, 256 thr, 8 warps 2x4,
// warp tile 64x32 -> 4x4 m16n8k8. Register-prefetch double buffering.
// grid = (N/128, M/128, 2 dirs)
// =====================================================================
__global__ __launch_bounds__(256) void xg_gemm_kernel(
    const float* __restrict__ x_in, int inp_sel,
    const float* __restrict__ w_f, const float* __restrict__ w_b,
    const float* __restrict__ bi_f, const float* __restrict__ bh_f,
    const float* __restrict__ bi_b, const float* __restrict__ bh_b)
{
    const int dir = blockIdx.z;
    const float* __restrict__ A  = (inp_sel < 0) ? x_in : g_io[inp_sel];
    const float* __restrict__ W  = dir ? w_b : w_f;
    const float* __restrict__ bi = dir ? bi_b : bi_f;
    const float* __restrict__ bh = dir ? bh_b : bh_f;
    float* __restrict__ C = g_xg[dir];

    const int n0 = blockIdx.x * 128;
    const int m0 = blockIdx.y * 128;

    __shared__ uint32_t As[128][20];
    __shared__ uint32_t Bs[128][20];

    const int tid  = threadIdx.x;
    const int lane = tid & 31;
    const int warp = tid >> 5;
    const int wm   = (warp & 1) * 64;
    const int wn   = (warp >> 1) * 32;
    const int gid  = lane >> 2;
    const int t4   = lane & 3;

    float acc[4][4][4];
#pragma unroll
    for (int i = 0; i < 4; i++)
#pragma unroll
        for (int j = 0; j < 4; j++)
#pragma unroll
            for (int k = 0; k < 4; k++) acc[i][j][k] = 0.0f;

    int lr[2], lc[2];
#pragma unroll
    for (int it = 0; it < 2; it++) {
        int idx = tid + it * 256;
        lr[it] = idx >> 2;
        lc[it] = (idx & 3) << 2;
    }

    float4 pa[2], pb[2];
#pragma unroll
    for (int it = 0; it < 2; it++) {
        pa[it] = *(const float4*)(A + (size_t)(m0 + lr[it]) * D_ + lc[it]);
        pb[it] = *(const float4*)(W + (size_t)(n0 + lr[it]) * D_ + lc[it]);
    }

    for (int k0 = 0; k0 < D_; k0 += 16) {
#pragma unroll
        for (int it = 0; it < 2; it++) {
            As[lr[it]][lc[it] + 0] = f2tf32(pa[it].x);
            As[lr[it]][lc[it] + 1] = f2tf32(pa[it].y);
            As[lr[it]][lc[it] + 2] = f2tf32(pa[it].z);
            As[lr[it]][lc[it] + 3] = f2tf32(pa[it].w);
            Bs[lr[it]][lc[it] + 0] = f2tf32(pb[it].x);
            Bs[lr[it]][lc[it] + 1] = f2tf32(pb[it].y);
            Bs[lr[it]][lc[it] + 2] = f2tf32(pb[it].z);
            Bs[lr[it]][lc[it] + 3] = f2tf32(pb[it].w);
        }
        __syncthreads();

        if (k0 + 16 < D_) {
            int kn = k0 + 16;
#pragma unroll
            for (int it = 0; it < 2; it++) {
                pa[it] = *(const float4*)(A + (size_t)(m0 + lr[it]) * D_ + kn + lc[it]);
                pb[it] = *(const float4*)(W + (size_t)(n0 + lr[it]) * D_ + kn + lc[it]);
            }
        }

#pragma unroll
        for (int kk = 0; kk < 16; kk += 8) {
            uint32_t af[4][4];
            uint32_t bf[4][2];
#pragma unroll
            for (int im = 0; im < 4; im++) {
                int mr = wm + im * 16;
                af[im][0] = As[mr + gid][kk + t4];
                af[im][1] = As[mr + gid + 8][kk + t4];
                af[im][2] = As[mr + gid][kk + t4 + 4];
                af[im][3] = As[mr + gid + 8][kk + t4 + 4];
            }
#pragma unroll
            for (int in_ = 0; in_ < 4; in_++) {
                int nr = wn + in_ * 8 + gid;
                bf[in_][0] = Bs[nr][kk + t4];
                bf[in_][1] = Bs[nr][kk + t4 + 4];
            }
#pragma unroll
            for (int im = 0; im < 4; im++)
#pragma unroll
                for (int in_ = 0; in_ < 4; in_++)
                    mma_tf32(acc[im][in_], af[im], bf[in_]);
        }
        __syncthreads();
    }

#pragma unroll
    for (int im = 0; im < 4; im++) {
#pragma unroll
        for (int in_ = 0; in_ < 4; in_++) {
            int m = m0 + wm + im * 16 + gid;
            int n = n0 + wn + in_ * 8 + t4 * 2;
            float b0v = bi[n] + bh[n];
            float b1v = bi[n + 1] + bh[n + 1];
            float2 r0 = make_float2(acc[im][in_][0] + b0v, acc[im][in_][1] + b1v);
            float2 r1 = make_float2(acc[im][in_][2] + b0v, acc[im][in_][3] + b1v);
            *(float2*)(C + (size_t)m * G_ + n)       = r0;
            *(float2*)(C + (size_t)(m + 8) * G_ + n) = r1;
        }
    }
}

// =====================================================================
// zero hidden state (both parities, both dirs) + barrier vars
// =====================================================================
__global__ void zero_state_kernel()
{
    int i = blockIdx.x * blockDim.x + threadIdx.x;
    float* hflat = &g_h[0][0][0];
    if (i < 4 * B_ * H_) hflat[i] = 0.0f;
    if (i < 2) { g_bar[i] = 0; g_gen[i] = 0; }
}

// =====================================================================
// persistent per-layer recurrent kernel.
// grid (48, 1, 2) = 96 CTAs, all co-resident (216KB smem -> 1 CTA/SM).
// Each CTA: W_hh slice (4 gates x 16 hidden = 64 rows x 768) resident in
// smem as tf32; loops all 256 steps with per-dir grid barrier.
// Per step: 64(batch) x 64(gate-units) x 768 tf32 mma, fused gates,
// cell state in registers.
// =====================================================================
__global__ __launch_bounds__(256, 1) void lstm_layer_kernel(
    const float* __restrict__ whf, const float* __restrict__ whb,
    const float* __restrict__ masks,
    float* __restrict__ dout, int out_sel, int layer)
{
    extern __shared__ uint32_t smem[];
    uint32_t* Ws = smem;                               // 64 x WS_STRIDE
    uint32_t* Asm = smem + 64 * WS_STRIDE;             // 2 x 64 x AS_STRIDE (double buf)
    float*    sC  = (float*)Asm;                       // aliased (64 x 68 floats, 17.4KB <= 18.4KB)

    const int dir = blockIdx.z;
    const int j0  = blockIdx.x * 16;
    const float* __restrict__ W = dir ? whb : whf;
    float* __restrict__ outseq = (out_sel >= 0) ? g_io[out_sel] : dout;

    const int tid  = threadIdx.x;
    const int lane = tid & 31;
    const int warp = tid >> 5;
    const int wm   = (warp & 1) * 32;
    const int wn   = (warp >> 1) * 16;
    const int gid  = lane >> 2;
    const int t4   = lane & 3;

    // ---- load W slice into smem (tf32), once ----
    for (int idx = tid; idx < 64 * 192; idx += 256) {
        int row = idx / 192;            // 0..63  (local n)
        int c4  = (idx % 192) * 4;      // 0..764
        int grow = (row >> 4) * H_ + j0 + (row & 15);
        float4 v = *(const float4*)(W + (size_t)grow * H_ + c4);
        Ws[row * WS_STRIDE + c4 + 0] = f2tf32(v.x);
        Ws[row * WS_STRIDE + c4 + 1] = f2tf32(v.y);
        Ws[row * WS_STRIDE + c4 + 2] = f2tf32(v.z);
        Ws[row * WS_STRIDE + c4 + 3] = f2tf32(v.w);
    }
    __syncthreads();

    // h-tile loader indices: 2 float4 per thread per BK=32 tile
    int lr[2], lc[2];
#pragma unroll
    for (int it = 0; it < 2; it++) {
        int idx = tid + it * 256;
        lr[it] = idx >> 3;              // 0..63 (batch row)
        lc[it] = (idx & 7) << 2;        // 0..28
    }

    // cell state in registers: thread handles (b,jj) pairs p = tid + it*256
    float ch[4] = {0.0f, 0.0f, 0.0f, 0.0f};

    int lgen = 0;

    for (int s = 0; s < T_; s++) {
        const int t = dir ? (T_ - 1 - s) : s;
        const float* __restrict__ hin = g_h[s & 1][dir];
        float* __restrict__ hout = g_h[(s & 1) ^ 1][dir];
        const float* __restrict__ xg = g_xg[dir] + (size_t)t * B_ * G_;

        float acc[2][2][4];
#pragma unroll
        for (int i = 0; i < 2; i++)
#pragma unroll
            for (int j = 0; j < 2; j++)
#pragma unroll
                for (int k = 0; k < 4; k++) acc[i][j][k] = 0.0f;

        // prefetch first tile (L2-only: peer-CTA writes are not in our L1)
        float4 pa[2];
#pragma unroll
        for (int it = 0; it < 2; it++)
            pa[it] = __ldcg((const float4*)(hin + (size_t)lr[it] * H_ + lc[it]));

        for (int k0 = 0; k0 < H_; k0 += 32) {
            uint32_t* Ab = Asm + ((k0 >> 5) & 1) * (64 * AS_STRIDE);
#pragma unroll
            for (int it = 0; it < 2; it++) {
                uint32_t* p = Ab + lr[it] * AS_STRIDE + lc[it];
                p[0] = f2tf32(pa[it].x);
                p[1] = f2tf32(pa[it].y);
                p[2] = f2tf32(pa[it].z);
                p[3] = f2tf32(pa[it].w);
            }
            if (k0 + 32 < H_) {
                int kn = k0 + 32;
#pragma unroll
                for (int it = 0; it < 2; it++)
                    pa[it] = __ldcg((const float4*)(hin + (size_t)lr[it] * H_ + kn + lc[it]));
            }
            __syncthreads();

#pragma unroll
            for (int kk = 0; kk < 32; kk += 8) {
                uint32_t af[2][4];
                uint32_t bf2[2][2];
#pragma unroll
                for (int im = 0; im < 2; im++) {
                    int mr = wm + im * 16;
                    af[im][0] = Ab[(mr + gid) * AS_STRIDE + kk + t4];
                    af[im][1] = Ab[(mr + gid + 8) * AS_STRIDE + kk + t4];
                    af[im][2] = Ab[(mr + gid) * AS_STRIDE + kk + t4 + 4];
                    af[im][3] = Ab[(mr + gid + 8) * AS_STRIDE + kk + t4 + 4];
                }
#pragma unroll
                for (int in_ = 0; in_ < 2; in_++) {
                    int nr = wn + in_ * 8 + gid;
                    bf2[in_][0] = Ws[nr * WS_STRIDE + k0 + kk + t4];
                    bf2[in_][1] = Ws[nr * WS_STRIDE + k0 + kk + t4 + 4];
                }
#pragma unroll
                for (int im = 0; im < 2; im++)
#pragma unroll
                    for (int in_ = 0; in_ < 2; in_++)
                        mma_tf32(acc[im][in_], af[im], bf2[in_]);
            }
        }
        __syncthreads();   // all mma done before sC (aliases A buffers) is written

        // spill C tile to smem
#pragma unroll
        for (int im = 0; im < 2; im++) {
#pragma unroll
            for (int in_ = 0; in_ < 2; in_++) {
                int m = wm + im * 16 + gid;
                int n = wn + in_ * 8 + t4 * 2;
                sC[m * 68 + n]           = acc[im][in_][0];
                sC[m * 68 + n + 1]       = acc[im][in_][1];
                sC[(m + 8) * 68 + n]     = acc[im][in_][2];
                sC[(m + 8) * 68 + n + 1] = acc[im][in_][3];
            }
        }
        __syncthreads();

        // fused gates + state update: thread owns 4 fixed (b,jj) pairs
#pragma unroll
        for (int it = 0; it < 4; it++) {
            int p  = tid + it * 256;
            int b  = p >> 4;
            int jj = p & 15;
            int j  = j0 + jj;
            const float* xb = xg + (size_t)b * G_;
            float yi = sC[b * 68 + jj]      + xb[j];
            float yf = sC[b * 68 + 16 + jj] + xb[H_ + j];
            float yg = sC[b * 68 + 32 + jj] + xb[2 * H_ + j];
            float yo = sC[b * 68 + 48 + jj] + xb[3 * H_ + j];
            float ig = sigmoidf_(yi);
            float fg = sigmoidf_(yf);
            float gg = tanhf(yg);
            float og = sigmoidf_(yo);
            float craw = fg * ch[it] + ig * gg;
            float hraw = og * tanhf(craw);
            float mt = masks[t * B_ + b];
            float h2 = hraw * mt;
            float c2 = craw * mt;
            ch[it] = c2;
            hout[b * H_ + j] = h2;
            outseq[(size_t)t * B_ * 2 * H_ + (size_t)b * 2 * H_ + dir * H_ + j] = h2;
            if (s == T_ - 1) {
                float* hn = dout + (size_t)TB_ * 2 * H_;
                float* cn = hn + (size_t)L_ * B_ * 2 * H_;
                size_t off = (size_t)layer * B_ * 2 * H_ + (size_t)b * 2 * H_ + dir * H_ + j;
                hn[off] = h2;
                cn[off] = c2;
            }
        }

        if (s == T_ - 1) break;

        // ---- per-dir grid barrier ----
        __threadfence();
        __syncthreads();
        if (tid == 0) {
            int a = atomicAdd(&g_bar[dir], 1);
            if (a == NCTA_DIR - 1) {
                atomicExch(&g_bar[dir], 0);
                __threadfence();
                atomicExch(&g_gen[dir], lgen + 1);
            } else {
                while (atomicAdd(&g_gen[dir], 0) <= lgen) { __nanosleep(64); }
                __threadfence();
            }
        }
        lgen++;
        __syncthreads();
    }
}

// =====================================================================
// launch
// =====================================================================
extern "C" void kernel_launch(void* const* d_in, const int* in_sizes, int n_in,
                              void* d_out, int out_size)
{
    const float* x      = (const float*)d_in[0];
    const float* masks  = (const float*)d_in[1];
    const float* w_ih_f = (const float*)d_in[2];
    const float* w_hh_f = (const float*)d_in[3];
    const float* b_ih_f = (const float*)d_in[4];
    const float* b_hh_f = (const float*)d_in[5];
    const float* w_ih_b = (const float*)d_in[6];
    const float* w_hh_b = (const float*)d_in[7];
    const float* b_ih_b = (const float*)d_in[8];
    const float* b_hh_b = (const float*)d_in[9];
    float* out = (float*)d_out;

    static int smem_set = 0;
    if (!smem_set) {
        cudaFuncSetAttribute(lstm_layer_kernel,
                             cudaFuncAttributeMaxDynamicSharedMemorySize, SMEM_BYTES);
        smem_set = 1;
    }

    for (int l = 0; l < L_; l++) {
        int inp_sel = (l == 0) ? -1 : (l - 1);
        int out_sel = (l == L_ - 1) ? -1 : l;

        dim3 gg(G_ / 128, TB_ / 128, 2);
        xg_gemm_kernel<<<gg, 256>>>(
            x, inp_sel,
            w_ih_f + (size_t)l * G_ * D_, w_ih_b + (size_t)l * G_ * D_,
            b_ih_f + (size_t)l * G_,      b_hh_f + (size_t)l * G_,
            b_ih_b + (size_t)l * G_,      b_hh_b + (size_t)l * G_);

        zero_state_kernel<<<(4 * B_ * H_ + 255) / 256, 256>>>();

        dim3 gs(NCTA_DIR, 1, 2);
        lstm_layer_kernel<<<gs, 256, SMEM_BYTES>>>(
            w_hh_f + (size_t)l * G_ * H_, w_hh_b + (size_t)l * G_ * H_,
            masks, out, out_sel, l);
    }
}

// round 6
// speedup vs baseline: 1.0799x; 1.0799x over previous
#include <cuda_runtime.h>
#include <cstdint>

#define T_  256
#define B_  64
#define H_  768
#define D_  1536
#define L_  3
#define G_  3072      // 4*H
#define TB_ 16384     // T*B

#define NCTA_DIR 48
#define WS_STRIDE 772          // 768 + 4 pad (words)
#define AS_STRIDE 36           // 32 + 4 pad (words)
#define SMEM_WORDS (64 * WS_STRIDE + 2 * 64 * AS_STRIDE)
#define SMEM_BYTES (SMEM_WORDS * 4)

// xg GEMM pipeline: 3 stages x (128x36 A + 128x36 B) floats
#define XG_STAGES 3
#define XG_STRIDE 36
#define XG_STAGE_WORDS (128 * XG_STRIDE)
#define XG_SMEM_BYTES (XG_STAGES * 2 * XG_STAGE_WORDS * 4)   // 110592

// ---------------- scratch (__device__ globals: allocation-free rule) ----------------
__device__ __align__(256) float g_xg[2][TB_ * G_];       // per-dir input projections
__device__ __align__(256) float g_io[2][TB_ * 2 * H_];   // layer ping-pong buffers
__device__ __align__(256) float g_h[2][2][B_ * H_];      // [parity][dir] hidden state
__device__ int g_bar[2];
__device__ int g_gen[2];

// ---------------- helpers ----------------
__device__ __forceinline__ uint32_t f2tf32(float x) {
    uint32_t u;
    asm("cvt.rna.tf32.f32 %0, %1;" : "=r"(u) : "f"(x));
    return u;
}

__device__ __forceinline__ void mma_tf32(float c[4], const uint32_t a[4], const uint32_t b[2]) {
    asm volatile(
        "mma.sync.aligned.m16n8k8.row.col.f32.tf32.tf32.f32 "
        "{%0,%1,%2,%3}, {%4,%5,%6,%7}, {%8,%9}, {%0,%1,%2,%3};\n"
        : "+f"(c[0]), "+f"(c[1]), "+f"(c[2]), "+f"(c[3])
        : "r"(a[0]), "r"(a[1]), "r"(a[2]), "r"(a[3]), "r"(b[0]), "r"(b[1]));
}

__device__ __forceinline__ float sigmoidf_(float x) {
    return 1.0f / (1.0f + __expf(-x));
}

__device__ __forceinline__ void cp16(float* s, const float* g) {
    uint32_t sa = (uint32_t)__cvta_generic_to_shared(s);
    asm volatile("cp.async.cg.shared.global [%0], [%1], 16;" :: "r"(sa), "l"(g));
}

// =====================================================================
// xg GEMM v2: 3-stage cp.async pipeline, BK=32.
// xg[m,n] = sum_k A[m,k]*W[n,k] + b_ih[n] + b_hh[n]
// M=TB_, N=G_, K=D_. BM=128,BN=128. 256 thr, 8 warps 2(M)x4(N),
// warp tile 64x32 -> 4x4 m16n8k8. tf32 cvt at fragment load.
// grid = (N/128, M/128, 2 dirs)
// =====================================================================
__global__ __launch_bounds__(256, 2) void xg_gemm_kernel(
    const float* __restrict__ x_in, int inp_sel,
    const float* __restrict__ w_f, const float* __restrict__ w_b,
    const float* __restrict__ bi_f, const float* __restrict__ bh_f,
    const float* __restrict__ bi_b, const float* __restrict__ bh_b)
{
    const int dir = blockIdx.z;
    const float* __restrict__ A  = (inp_sel < 0) ? x_in : g_io[inp_sel];
    const float* __restrict__ W  = dir ? w_b : w_f;
    const float* __restrict__ bi = dir ? bi_b : bi_f;
    const float* __restrict__ bh = dir ? bh_b : bh_f;
    float* __restrict__ C = g_xg[dir];

    const int n0 = blockIdx.x * 128;
    const int m0 = blockIdx.y * 128;

    extern __shared__ float xsm[];
    float* AsBase = xsm;                                  // [3][128][36]
    float* BsBase = xsm + XG_STAGES * XG_STAGE_WORDS;     // [3][128][36]

    const int tid  = threadIdx.x;
    const int lane = tid & 31;
    const int warp = tid >> 5;
    const int wm   = (warp & 1) * 64;
    const int wn   = (warp >> 1) * 32;
    const int gid  = lane >> 2;
    const int t4   = lane & 3;

    float acc[4][4][4];
#pragma unroll
    for (int i = 0; i < 4; i++)
#pragma unroll
        for (int j = 0; j < 4; j++)
#pragma unroll
            for (int k = 0; k < 4; k++) acc[i][j][k] = 0.0f;

    // loader mapping: 1024 16B-chunks per tile per matrix, 4 per thread
    int lrow[4], lcol[4];
#pragma unroll
    for (int i = 0; i < 4; i++) {
        int id = tid + i * 256;
        lrow[i] = id >> 3;          // 0..127
        lcol[i] = (id & 7) * 4;     // 0,4,...,28
    }

    const int NT = D_ / 32;   // 48

#define XG_LOAD_STAGE(st, k0)                                              \
    do {                                                                   \
        float* as_ = AsBase + (st) * XG_STAGE_WORDS;                       \
        float* bs_ = BsBase + (st) * XG_STAGE_WORDS;                       \
        _Pragma("unroll")                                                  \
        for (int i_ = 0; i_ < 4; i_++) {                                   \
            cp16(as_ + lrow[i_] * XG_STRIDE + lcol[i_],                    \
                 A + (size_t)(m0 + lrow[i_]) * D_ + (k0) + lcol[i_]);      \
            cp16(bs_ + lrow[i_] * XG_STRIDE + lcol[i_],                    \
                 W + (size_t)(n0 + lrow[i_]) * D_ + (k0) + lcol[i_]);      \
        }                                                                  \
        asm volatile("cp.async.commit_group;");                            \
    } while (0)

    XG_LOAD_STAGE(0, 0);
    XG_LOAD_STAGE(1, 32);

#pragma unroll 1
    for (int it = 0; it < NT; it++) {
        if (it + 1 < NT) asm volatile("cp.async.wait_group 1;");
        else             asm volatile("cp.async.wait_group 0;");
        __syncthreads();

        if (it + 2 < NT) {
            int st = (it + 2) % XG_STAGES;
            XG_LOAD_STAGE(st, (it + 2) * 32);
        }

        const float* Af = AsBase + (it % XG_STAGES) * XG_STAGE_WORDS;
        const float* Bf = BsBase + (it % XG_STAGES) * XG_STAGE_WORDS;

#pragma unroll
        for (int kk = 0; kk < 32; kk += 8) {
            uint32_t af[4][4];
            uint32_t bf[4][2];
#pragma unroll
            for (int im = 0; im < 4; im++) {
                int mr = wm + im * 16;
                af[im][0] = f2tf32(Af[(mr + gid)     * XG_STRIDE + kk + t4]);
                af[im][1] = f2tf32(Af[(mr + gid + 8) * XG_STRIDE + kk + t4]);
                af[im][2] = f2tf32(Af[(mr + gid)     * XG_STRIDE + kk + t4 + 4]);
                af[im][3] = f2tf32(Af[(mr + gid + 8) * XG_STRIDE + kk + t4 + 4]);
            }
#pragma unroll
            for (int in_ = 0; in_ < 4; in_++) {
                int nr = wn + in_ * 8 + gid;
                bf[in_][0] = f2tf32(Bf[nr * XG_STRIDE + kk + t4]);
                bf[in_][1] = f2tf32(Bf[nr * XG_STRIDE + kk + t4 + 4]);
            }
#pragma unroll
            for (int im = 0; im < 4; im++)
#pragma unroll
                for (int in_ = 0; in_ < 4; in_++)
                    mma_tf32(acc[im][in_], af[im], bf[in_]);
        }
    }
#undef XG_LOAD_STAGE

    // epilogue: add combined bias, store
#pragma unroll
    for (int im = 0; im < 4; im++) {
#pragma unroll
        for (int in_ = 0; in_ < 4; in_++) {
            int m = m0 + wm + im * 16 + gid;
            int n = n0 + wn + in_ * 8 + t4 * 2;
            float b0v = bi[n] + bh[n];
            float b1v = bi[n + 1] + bh[n + 1];
            float2 r0 = make_float2(acc[im][in_][0] + b0v, acc[im][in_][1] + b1v);
            float2 r1 = make_float2(acc[im][in_][2] + b0v, acc[im][in_][3] + b1v);
            *(float2*)(C + (size_t)m * G_ + n)       = r0;
            *(float2*)(C + (size_t)(m + 8) * G_ + n) = r1;
        }
    }
}

// =====================================================================
// zero hidden state (both parities, both dirs) + barrier vars
// =====================================================================
__global__ void zero_state_kernel()
{
    int i = blockIdx.x * blockDim.x + threadIdx.x;
    float* hflat = &g_h[0][0][0];
    if (i < 4 * B_ * H_) hflat[i] = 0.0f;
    if (i < 2) { g_bar[i] = 0; g_gen[i] = 0; }
}

// =====================================================================
// persistent per-layer recurrent kernel (passing R4 version).
// grid (48, 1, 2) = 96 CTAs, all co-resident. W_hh slice smem-resident,
// cell state in registers, per-dir grid barrier between steps.
// =====================================================================
__global__ __launch_bounds__(256, 1) void lstm_layer_kernel(
    const float* __restrict__ whf, const float* __restrict__ whb,
    const float* __restrict__ masks,
    float* __restrict__ dout, int out_sel, int layer)
{
    extern __shared__ uint32_t smem[];
    uint32_t* Ws = smem;                               // 64 x WS_STRIDE
    uint32_t* Asm = smem + 64 * WS_STRIDE;             // 2 x 64 x AS_STRIDE (double buf)
    float*    sC  = (float*)Asm;                       // aliased

    const int dir = blockIdx.z;
    const int j0  = blockIdx.x * 16;
    const float* __restrict__ W = dir ? whb : whf;
    float* __restrict__ outseq = (out_sel >= 0) ? g_io[out_sel] : dout;

    const int tid  = threadIdx.x;
    const int lane = tid & 31;
    const int warp = tid >> 5;
    const int wm   = (warp & 1) * 32;
    const int wn   = (warp >> 1) * 16;
    const int gid  = lane >> 2;
    const int t4   = lane & 3;

    // ---- load W slice into smem (tf32), once ----
    for (int idx = tid; idx < 64 * 192; idx += 256) {
        int row = idx / 192;
        int c4  = (idx % 192) * 4;
        int grow = (row >> 4) * H_ + j0 + (row & 15);
        float4 v = *(const float4*)(W + (size_t)grow * H_ + c4);
        Ws[row * WS_STRIDE + c4 + 0] = f2tf32(v.x);
        Ws[row * WS_STRIDE + c4 + 1] = f2tf32(v.y);
        Ws[row * WS_STRIDE + c4 + 2] = f2tf32(v.z);
        Ws[row * WS_STRIDE + c4 + 3] = f2tf32(v.w);
    }
    __syncthreads();

    int lr[2], lc[2];
#pragma unroll
    for (int it = 0; it < 2; it++) {
        int idx = tid + it * 256;
        lr[it] = idx >> 3;
        lc[it] = (idx & 7) << 2;
    }

    float ch[4] = {0.0f, 0.0f, 0.0f, 0.0f};
    int lgen = 0;

    for (int s = 0; s < T_; s++) {
        const int t = dir ? (T_ - 1 - s) : s;
        const float* __restrict__ hin = g_h[s & 1][dir];
        float* __restrict__ hout = g_h[(s & 1) ^ 1][dir];
        const float* __restrict__ xg = g_xg[dir] + (size_t)t * B_ * G_;

        float acc[2][2][4];
#pragma unroll
        for (int i = 0; i < 2; i++)
#pragma unroll
            for (int j = 0; j < 2; j++)
#pragma unroll
                for (int k = 0; k < 4; k++) acc[i][j][k] = 0.0f;

        float4 pa[2];
#pragma unroll
        for (int it = 0; it < 2; it++)
            pa[it] = __ldcg((const float4*)(hin + (size_t)lr[it] * H_ + lc[it]));

        for (int k0 = 0; k0 < H_; k0 += 32) {
            uint32_t* Ab = Asm + ((k0 >> 5) & 1) * (64 * AS_STRIDE);
#pragma unroll
            for (int it = 0; it < 2; it++) {
                uint32_t* p = Ab + lr[it] * AS_STRIDE + lc[it];
                p[0] = f2tf32(pa[it].x);
                p[1] = f2tf32(pa[it].y);
                p[2] = f2tf32(pa[it].z);
                p[3] = f2tf32(pa[it].w);
            }
            if (k0 + 32 < H_) {
                int kn = k0 + 32;
#pragma unroll
                for (int it = 0; it < 2; it++)
                    pa[it] = __ldcg((const float4*)(hin + (size_t)lr[it] * H_ + kn + lc[it]));
            }
            __syncthreads();

#pragma unroll
            for (int kk = 0; kk < 32; kk += 8) {
                uint32_t af[2][4];
                uint32_t bf2[2][2];
#pragma unroll
                for (int im = 0; im < 2; im++) {
                    int mr = wm + im * 16;
                    af[im][0] = Ab[(mr + gid) * AS_STRIDE + kk + t4];
                    af[im][1] = Ab[(mr + gid + 8) * AS_STRIDE + kk + t4];
                    af[im][2] = Ab[(mr + gid) * AS_STRIDE + kk + t4 + 4];
                    af[im][3] = Ab[(mr + gid + 8) * AS_STRIDE + kk + t4 + 4];
                }
#pragma unroll
                for (int in_ = 0; in_ < 2; in_++) {
                    int nr = wn + in_ * 8 + gid;
                    bf2[in_][0] = Ws[nr * WS_STRIDE + k0 + kk + t4];
                    bf2[in_][1] = Ws[nr * WS_STRIDE + k0 + kk + t4 + 4];
                }
#pragma unroll
                for (int im = 0; im < 2; im++)
#pragma unroll
                    for (int in_ = 0; in_ < 2; in_++)
                        mma_tf32(acc[im][in_], af[im], bf2[in_]);
            }
        }
        __syncthreads();

#pragma unroll
        for (int im = 0; im < 2; im++) {
#pragma unroll
            for (int in_ = 0; in_ < 2; in_++) {
                int m = wm + im * 16 + gid;
                int n = wn + in_ * 8 + t4 * 2;
                sC[m * 68 + n]           = acc[im][in_][0];
                sC[m * 68 + n + 1]       = acc[im][in_][1];
                sC[(m + 8) * 68 + n]     = acc[im][in_][2];
                sC[(m + 8) * 68 + n + 1] = acc[im][in_][3];
            }
        }
        __syncthreads();

#pragma unroll
        for (int it = 0; it < 4; it++) {
            int p  = tid + it * 256;
            int b  = p >> 4;
            int jj = p & 15;
            int j  = j0 + jj;
            const float* xb = xg + (size_t)b * G_;
            float yi = sC[b * 68 + jj]      + xb[j];
            float yf = sC[b * 68 + 16 + jj] + xb[H_ + j];
            float yg = sC[b * 68 + 32 + jj] + xb[2 * H_ + j];
            float yo = sC[b * 68 + 48 + jj] + xb[3 * H_ + j];
            float ig = sigmoidf_(yi);
            float fg = sigmoidf_(yf);
            float gg = tanhf(yg);
            float og = sigmoidf_(yo);
            float craw = fg * ch[it] + ig * gg;
            float hraw = og * tanhf(craw);
            float mt = masks[t * B_ + b];
            float h2 = hraw * mt;
            float c2 = craw * mt;
            ch[it] = c2;
            hout[b * H_ + j] = h2;
            outseq[(size_t)t * B_ * 2 * H_ + (size_t)b * 2 * H_ + dir * H_ + j] = h2;
            if (s == T_ - 1) {
                float* hn = dout + (size_t)TB_ * 2 * H_;
                float* cn = hn + (size_t)L_ * B_ * 2 * H_;
                size_t off = (size_t)layer * B_ * 2 * H_ + (size_t)b * 2 * H_ + dir * H_ + j;
                hn[off] = h2;
                cn[off] = c2;
            }
        }

        if (s == T_ - 1) break;

        __threadfence();
        __syncthreads();
        if (tid == 0) {
            int a = atomicAdd(&g_bar[dir], 1);
            if (a == NCTA_DIR - 1) {
                atomicExch(&g_bar[dir], 0);
                __threadfence();
                atomicExch(&g_gen[dir], lgen + 1);
            } else {
                while (atomicAdd(&g_gen[dir], 0) <= lgen) { __nanosleep(64); }
                __threadfence();
            }
        }
        lgen++;
        __syncthreads();
    }
}

// =====================================================================
// launch
// =====================================================================
extern "C" void kernel_launch(void* const* d_in, const int* in_sizes, int n_in,
                              void* d_out, int out_size)
{
    const float* x      = (const float*)d_in[0];
    const float* masks  = (const float*)d_in[1];
    const float* w_ih_f = (const float*)d_in[2];
    const float* w_hh_f = (const float*)d_in[3];
    const float* b_ih_f = (const float*)d_in[4];
    const float* b_hh_f = (const float*)d_in[5];
    const float* w_ih_b = (const float*)d_in[6];
    const float* w_hh_b = (const float*)d_in[7];
    const float* b_ih_b = (const float*)d_in[8];
    const float* b_hh_b = (const float*)d_in[9];
    float* out = (float*)d_out;

    // idempotent, not a stream op: safe under graph capture, no static guards
    cudaFuncSetAttribute(lstm_layer_kernel,
                         cudaFuncAttributeMaxDynamicSharedMemorySize, SMEM_BYTES);
    cudaFuncSetAttribute(xg_gemm_kernel,
                         cudaFuncAttributeMaxDynamicSharedMemorySize, XG_SMEM_BYTES);

    for (int l = 0; l < L_; l++) {
        int inp_sel = (l == 0) ? -1 : (l - 1);
        int out_sel = (l == L_ - 1) ? -1 : l;

        dim3 gg(G_ / 128, TB_ / 128, 2);
        xg_gemm_kernel<<<gg, 256, XG_SMEM_BYTES>>>(
            x, inp_sel,
            w_ih_f + (size_t)l * G_ * D_, w_ih_b + (size_t)l * G_ * D_,
            b_ih_f + (size_t)l * G_,      b_hh_f + (size_t)l * G_,
            b_ih_b + (size_t)l * G_,      b_hh_b + (size_t)l * G_);

        zero_state_kernel<<<(4 * B_ * H_ + 255) / 256, 256>>>();

        dim3 gs(NCTA_DIR, 1, 2);
        lstm_layer_kernel<<<gs, 256, SMEM_BYTES>>>(
            w_hh_f + (size_t)l * G_ * H_, w_hh_b + (size_t)l * G_ * H_,
            masks, out, out_sel, l);
    }
}

// round 8
// speedup vs baseline: 1.3922x; 1.2892x over previous
#include <cuda_runtime.h>
#include <cstdint>

#define T_  256
#define B_  64
#define H_  768
#define D_  1536
#define L_  3
#define G_  3072      // 4*H
#define TB_ 16384     // T*B

#define NCTA_DIR 48
#define WS_STRIDE 772          // 768 + 4 pad (words)
#define AS_STRIDE 36           // 32 + 4 pad (words)
#define R_STAGES 3
#define R_SMEM_WORDS (64 * WS_STRIDE + R_STAGES * 64 * AS_STRIDE)
#define R_SMEM_BYTES (R_SMEM_WORDS * 4)     // 225280

// xg GEMM pipeline: 3 stages x (128x36 A + 128x36 B) floats
#define XG_STAGES 3
#define XG_STRIDE 36
#define XG_STAGE_WORDS (128 * XG_STRIDE)
#define XG_SMEM_BYTES (XG_STAGES * 2 * XG_STAGE_WORDS * 4)   // 110592

// ---------------- scratch (__device__ globals: allocation-free rule) ----------------
__device__ __align__(256) float g_xg[2][TB_ * G_];       // per-dir input projections
__device__ __align__(256) float g_io[2][TB_ * 2 * H_];   // layer ping-pong (tf32-rounded)
__device__ __align__(256) float g_h[2][2][B_ * H_];      // [parity][dir] hidden (tf32-rounded)
__device__ __align__(256) float g_xr[TB_ * D_];          // tf32-rounded x
__device__ __align__(256) float g_wr[2][L_ * G_ * D_];   // tf32-rounded w_ih per dir
__device__ __align__(256) float g_bias[2][L_ * G_];      // combined biases per dir
__device__ int g_bar[2];

// ---------------- helpers ----------------
__device__ __forceinline__ uint32_t f2tf32(float x) {
    uint32_t u;
    asm("cvt.rna.tf32.f32 %0, %1;" : "=r"(u) : "f"(x));
    return u;
}
__device__ __forceinline__ float rnd_tf32(float x) {
    return __uint_as_float(f2tf32(x));
}

__device__ __forceinline__ void mma_tf32(float c[4], const uint32_t a[4], const uint32_t b[2]) {
    asm volatile(
        "mma.sync.aligned.m16n8k8.row.col.f32.tf32.tf32.f32 "
        "{%0,%1,%2,%3}, {%4,%5,%6,%7}, {%8,%9}, {%0,%1,%2,%3};\n"
        : "+f"(c[0]), "+f"(c[1]), "+f"(c[2]), "+f"(c[3])
        : "r"(a[0]), "r"(a[1]), "r"(a[2]), "r"(a[3]), "r"(b[0]), "r"(b[1]));
}

__device__ __forceinline__ float sigmoidf_(float x) {
    return 1.0f / (1.0f + __expf(-x));
}

__device__ __forceinline__ void cp16(float* s, const float* g) {
    uint32_t sa = (uint32_t)__cvta_generic_to_shared(s);
    asm volatile("cp.async.cg.shared.global [%0], [%1], 16;" :: "r"(sa), "l"(g));
}

__device__ __forceinline__ uint32_t cvta_s(const void* p) {
    return (uint32_t)__cvta_generic_to_shared(p);
}

__device__ __forceinline__ void ldsm4(uint32_t& r0, uint32_t& r1, uint32_t& r2, uint32_t& r3,
                                      uint32_t addr) {
    asm volatile("ldmatrix.sync.aligned.m8n8.x4.shared.b16 {%0,%1,%2,%3}, [%4];"
                 : "=r"(r0), "=r"(r1), "=r"(r2), "=r"(r3) : "r"(addr));
}

__device__ __forceinline__ void arrive_release(int* p) {
    asm volatile("red.release.gpu.global.add.s32 [%0], 1;" :: "l"(p) : "memory");
}
__device__ __forceinline__ int ld_acq(const int* p) {
    int v;
    asm volatile("ld.acquire.gpu.global.s32 %0, [%1];" : "=r"(v) : "l"(p) : "memory");
    return v;
}

// =====================================================================
// pre-round x, w_ih (both dirs, all layers) to tf32; combine biases.
// =====================================================================
__global__ void preround_kernel(
    const float4* __restrict__ x,
    const float4* __restrict__ wf, const float4* __restrict__ wb,
    const float4* __restrict__ bif, const float4* __restrict__ bhf,
    const float4* __restrict__ bib, const float4* __restrict__ bhb)
{
    const int stride = gridDim.x * blockDim.x;
    const int g0 = blockIdx.x * blockDim.x + threadIdx.x;

    float4* xr = (float4*)g_xr;
    for (int i = g0; i < TB_ * D_ / 4; i += stride) {
        float4 v = x[i];
        v.x = rnd_tf32(v.x); v.y = rnd_tf32(v.y);
        v.z = rnd_tf32(v.z); v.w = rnd_tf32(v.w);
        xr[i] = v;
    }
    float4* w0 = (float4*)g_wr[0];
    float4* w1 = (float4*)g_wr[1];
    for (int i = g0; i < L_ * G_ * D_ / 4; i += stride) {
        float4 a = wf[i];
        a.x = rnd_tf32(a.x); a.y = rnd_tf32(a.y);
        a.z = rnd_tf32(a.z); a.w = rnd_tf32(a.w);
        w0[i] = a;
        float4 b = wb[i];
        b.x = rnd_tf32(b.x); b.y = rnd_tf32(b.y);
        b.z = rnd_tf32(b.z); b.w = rnd_tf32(b.w);
        w1[i] = b;
    }
    float4* b0 = (float4*)g_bias[0];
    float4* b1 = (float4*)g_bias[1];
    for (int i = g0; i < L_ * G_ / 4; i += stride) {
        float4 p = bif[i], q = bhf[i];
        b0[i] = make_float4(p.x + q.x, p.y + q.y, p.z + q.z, p.w + q.w);
        float4 r = bib[i], s = bhb[i];
        b1[i] = make_float4(r.x + s.x, r.y + s.y, r.z + s.z, r.w + s.w);
    }
}

// =====================================================================
// xg GEMM v3: 3-stage cp.async, BK=32, ldmatrix fragments, no cvt
// (inputs pre-rounded). grid = (N/128, M/128, 2 dirs)
// =====================================================================
__global__ __launch_bounds__(256, 2) void xg_gemm_kernel(
    int inp_sel, int layer)
{
    const int dir = blockIdx.z;
    const float* __restrict__ A  = (inp_sel < 0) ? g_xr : g_io[inp_sel];
    const float* __restrict__ W  = g_wr[dir] + (size_t)layer * G_ * D_;
    const float* __restrict__ Bv = g_bias[dir] + (size_t)layer * G_;
    float* __restrict__ C = g_xg[dir];

    const int n0 = blockIdx.x * 128;
    const int m0 = blockIdx.y * 128;

    extern __shared__ float xsm[];
    float* AsBase = xsm;
    float* BsBase = xsm + XG_STAGES * XG_STAGE_WORDS;

    const int tid  = threadIdx.x;
    const int lane = tid & 31;
    const int warp = tid >> 5;
    const int wm   = (warp & 1) * 64;
    const int wn   = (warp >> 1) * 32;
    const int gid  = lane >> 2;
    const int t4   = lane & 3;
    const int gl   = lane >> 3;
    const int rl   = lane & 7;

    float acc[4][4][4];
#pragma unroll
    for (int i = 0; i < 4; i++)
#pragma unroll
        for (int j = 0; j < 4; j++)
#pragma unroll
            for (int k = 0; k < 4; k++) acc[i][j][k] = 0.0f;

    int lrow[4], lcol[4];
#pragma unroll
    for (int i = 0; i < 4; i++) {
        int id = tid + i * 256;
        lrow[i] = id >> 3;
        lcol[i] = (id & 7) * 4;
    }

    // ldmatrix lane-relative offsets (bytes)
    const uint32_t as_u = cvta_s(AsBase);
    const uint32_t bs_u = cvta_s(BsBase);
    const uint32_t aRel = ((((gl & 1) * 8 + rl) * XG_STRIDE) + (gl >> 1) * 4) * 4;
    const uint32_t bRel = ((((gl >> 1) * 8 + rl) * XG_STRIDE) + (gl & 1) * 4) * 4;

    const int NT = D_ / 32;   // 48

#define XG_LOAD_STAGE(st, k0)                                              \
    do {                                                                   \
        float* as_ = AsBase + (st) * XG_STAGE_WORDS;                       \
        float* bs_ = BsBase + (st) * XG_STAGE_WORDS;                       \
        _Pragma("unroll")                                                  \
        for (int i_ = 0; i_ < 4; i_++) {                                   \
            cp16(as_ + lrow[i_] * XG_STRIDE + lcol[i_],                    \
                 A + (size_t)(m0 + lrow[i_]) * D_ + (k0) + lcol[i_]);      \
            cp16(bs_ + lrow[i_] * XG_STRIDE + lcol[i_],                    \
                 W + (size_t)(n0 + lrow[i_]) * D_ + (k0) + lcol[i_]);      \
        }                                                                  \
        asm volatile("cp.async.commit_group;");                            \
    } while (0)

    XG_LOAD_STAGE(0, 0);
    XG_LOAD_STAGE(1, 32);

#pragma unroll 1
    for (int it = 0; it < NT; it++) {
        if (it + 1 < NT) asm volatile("cp.async.wait_group 1;");
        else             asm volatile("cp.async.wait_group 0;");
        __syncthreads();

        if (it + 2 < NT) {
            int st = (it + 2) % XG_STAGES;
            XG_LOAD_STAGE(st, (it + 2) * 32);
        }

        const int st = it % XG_STAGES;
        const uint32_t aBase = as_u + (st * XG_STAGE_WORDS + wm * XG_STRIDE) * 4 + aRel;
        const uint32_t bBase = bs_u + (st * XG_STAGE_WORDS + wn * XG_STRIDE) * 4 + bRel;

#pragma unroll
        for (int kk = 0; kk < 32; kk += 8) {
            uint32_t af[4][4];
            uint32_t bf[4][2];
#pragma unroll
            for (int im = 0; im < 4; im++)
                ldsm4(af[im][0], af[im][1], af[im][2], af[im][3],
                      aBase + (im * 16 * XG_STRIDE + kk) * 4);
#pragma unroll
            for (int j = 0; j < 2; j++) {
                uint32_t r0, r1, r2, r3;
                ldsm4(r0, r1, r2, r3, bBase + (j * 16 * XG_STRIDE + kk) * 4);
                bf[2 * j][0] = r0;  bf[2 * j][1] = r1;
                bf[2 * j + 1][0] = r2;  bf[2 * j + 1][1] = r3;
            }
#pragma unroll
            for (int im = 0; im < 4; im++)
#pragma unroll
                for (int in_ = 0; in_ < 4; in_++)
                    mma_tf32(acc[im][in_], af[im], bf[in_]);
        }
    }
#undef XG_LOAD_STAGE

    // epilogue: add combined bias, store
#pragma unroll
    for (int im = 0; im < 4; im++) {
#pragma unroll
        for (int in_ = 0; in_ < 4; in_++) {
            int m = m0 + wm + im * 16 + gid;
            int n = n0 + wn + in_ * 8 + t4 * 2;
            float b0v = Bv[n];
            float b1v = Bv[n + 1];
            float2 r0 = make_float2(acc[im][in_][0] + b0v, acc[im][in_][1] + b1v);
            float2 r1 = make_float2(acc[im][in_][2] + b0v, acc[im][in_][3] + b1v);
            *(float2*)(C + (size_t)m * G_ + n)       = r0;
            *(float2*)(C + (size_t)(m + 8) * G_ + n) = r1;
        }
    }
}

// =====================================================================
// zero hidden state (both parities, both dirs) + barrier counter
// =====================================================================
__global__ void zero_state_kernel()
{
    int i = blockIdx.x * blockDim.x + threadIdx.x;
    float* hflat = &g_h[0][0][0];
    if (i < 4 * B_ * H_) hflat[i] = 0.0f;
    if (i < 2) g_bar[i] = 0;
}

// =====================================================================
// persistent per-layer recurrent kernel v2.
// grid (48, 1, 2), 1 CTA/SM. W_hh slice smem-resident (tf32),
// h tiles via 3-stage cp.async (L2-only), ldmatrix fragments,
// light release/acquire grid barrier, xg prefetched during barrier.
// =====================================================================
__global__ __launch_bounds__(256, 1) void lstm_layer_kernel(
    const float* __restrict__ whf, const float* __restrict__ whb,
    const float* __restrict__ masks,
    float* __restrict__ dout, int out_sel, int layer)
{
    extern __shared__ uint32_t smem[];
    uint32_t* Ws  = smem;                              // 64 x WS_STRIDE
    float*    Asm = (float*)(smem + 64 * WS_STRIDE);   // R_STAGES x 64 x AS_STRIDE
    float*    sC  = Asm;                               // aliased (time-separated)

    const int dir = blockIdx.z;
    const int j0  = blockIdx.x * 16;
    const float* __restrict__ W = dir ? whb : whf;
    float* __restrict__ outseq = (out_sel >= 0) ? g_io[out_sel] : dout;

    const int tid  = threadIdx.x;
    const int lane = tid & 31;
    const int warp = tid >> 5;
    const int wm   = (warp & 1) * 32;
    const int wn   = (warp >> 1) * 16;
    const int gid  = lane >> 2;
    const int t4   = lane & 3;
    const int gl   = lane >> 3;
    const int rl   = lane & 7;

    // ---- load W slice into smem (tf32), once ----
    for (int idx = tid; idx < 64 * 192; idx += 256) {
        int row = idx / 192;
        int c4  = (idx % 192) * 4;
        int grow = (row >> 4) * H_ + j0 + (row & 15);
        float4 v = *(const float4*)(W + (size_t)grow * H_ + c4);
        Ws[row * WS_STRIDE + c4 + 0] = f2tf32(v.x);
        Ws[row * WS_STRIDE + c4 + 1] = f2tf32(v.y);
        Ws[row * WS_STRIDE + c4 + 2] = f2tf32(v.z);
        Ws[row * WS_STRIDE + c4 + 3] = f2tf32(v.w);
    }
    __syncthreads();

    // cp.async loader mapping: 2 x 16B chunks per thread per k-tile
    int lr[2], lc[2];
#pragma unroll
    for (int it = 0; it < 2; it++) {
        int idx = tid + it * 256;
        lr[it] = idx >> 3;
        lc[it] = (idx & 7) << 2;
    }

    // ldmatrix lane-relative offsets
    const uint32_t ws_u = cvta_s(Ws);
    const uint32_t as_u = cvta_s(Asm);
    const uint32_t bAddrBase = ws_u +
        (((wn + (gl >> 1) * 8 + rl) * WS_STRIDE) + (gl & 1) * 4) * 4;
    const uint32_t aRel = ((((gl & 1) * 8 + rl) * AS_STRIDE) + (gl >> 1) * 4) * 4;

    // epilogue ownership: 4 fixed (b, jj) pairs per thread
    int pb[4], pj[4];
#pragma unroll
    for (int it = 0; it < 4; it++) {
        int p = tid + it * 256;
        pb[it] = p >> 4;
        pj[it] = j0 + (p & 15);
    }

    float ch[4] = {0.0f, 0.0f, 0.0f, 0.0f};
    float xr_[16];
    float mr_[4];

    // prefetch xg + mask for step 0
    {
        int t0 = dir ? (T_ - 1) : 0;
        const float* xgb = g_xg[dir] + (size_t)t0 * B_ * G_;
#pragma unroll
        for (int it = 0; it < 4; it++) {
            const float* base = xgb + (size_t)pb[it] * G_ + pj[it];
            xr_[it * 4 + 0] = __ldg(base);
            xr_[it * 4 + 1] = __ldg(base + H_);
            xr_[it * 4 + 2] = __ldg(base + 2 * H_);
            xr_[it * 4 + 3] = __ldg(base + 3 * H_);
            mr_[it] = __ldg(&masks[t0 * B_ + pb[it]]);
        }
    }

    const int NT = H_ / 32;   // 24

#pragma unroll 1
    for (int s = 0; s < T_; s++) {
        const int t = dir ? (T_ - 1 - s) : s;
        const float* __restrict__ hin = g_h[s & 1][dir];
        float* __restrict__ hout = g_h[(s & 1) ^ 1][dir];

        float acc[2][2][4];
#pragma unroll
        for (int i = 0; i < 2; i++)
#pragma unroll
            for (int j = 0; j < 2; j++)
#pragma unroll
                for (int k = 0; k < 4; k++) acc[i][j][k] = 0.0f;

#define R_LOAD_STAGE(st, k0)                                             \
    do {                                                                 \
        float* as_ = Asm + (st) * (64 * AS_STRIDE);                      \
        _Pragma("unroll")                                                \
        for (int i_ = 0; i_ < 2; i_++)                                   \
            cp16(as_ + lr[i_] * AS_STRIDE + lc[i_],                      \
                 hin + (size_t)lr[i_] * H_ + (k0) + lc[i_]);             \
        asm volatile("cp.async.commit_group;");                          \
    } while (0)

        R_LOAD_STAGE(0, 0);
        R_LOAD_STAGE(1, 32);

#pragma unroll 1
        for (int kt = 0; kt < NT; kt++) {
            if (kt + 1 < NT) asm volatile("cp.async.wait_group 1;");
            else             asm volatile("cp.async.wait_group 0;");
            __syncthreads();

            if (kt + 2 < NT) {
                int st = (kt + 2) % R_STAGES;
                R_LOAD_STAGE(st, (kt + 2) * 32);
            }

            const int st = kt % R_STAGES;
            const uint32_t aBase = as_u + (st * (64 * AS_STRIDE) + wm * AS_STRIDE) * 4 + aRel;
            const uint32_t bK = bAddrBase + (kt * 32) * 4;

#pragma unroll
            for (int kk = 0; kk < 32; kk += 8) {
                uint32_t af[2][4];
                uint32_t b0, b1, b2, b3;
#pragma unroll
                for (int im = 0; im < 2; im++)
                    ldsm4(af[im][0], af[im][1], af[im][2], af[im][3],
                          aBase + (im * 16 * AS_STRIDE + kk) * 4);
                ldsm4(b0, b1, b2, b3, bK + kk * 4);
                {
                    uint32_t bf0[2] = {b0, b1};
                    uint32_t bf1[2] = {b2, b3};
                    mma_tf32(acc[0][0], af[0], bf0);
                    mma_tf32(acc[0][1], af[0], bf1);
                    mma_tf32(acc[1][0], af[1], bf0);
                    mma_tf32(acc[1][1], af[1], bf1);
                }
            }
        }
#undef R_LOAD_STAGE
        __syncthreads();   // all mma done before sC (aliases A stages) is written

        // spill C tile to smem
#pragma unroll
        for (int im = 0; im < 2; im++) {
#pragma unroll
            for (int in_ = 0; in_ < 2; in_++) {
                int m = wm + im * 16 + gid;
                int n = wn + in_ * 8 + t4 * 2;
                sC[m * 68 + n]           = acc[im][in_][0];
                sC[m * 68 + n + 1]       = acc[im][in_][1];
                sC[(m + 8) * 68 + n]     = acc[im][in_][2];
                sC[(m + 8) * 68 + n + 1] = acc[im][in_][3];
            }
        }
        __syncthreads();

        // fused gates + state update (xg/mask from prefetch registers)
#pragma unroll
        for (int it = 0; it < 4; it++) {
            int b  = pb[it];
            int jj = pj[it] - j0;
            int j  = pj[it];
            float yi = sC[b * 68 + jj]      + xr_[it * 4 + 0];
            float yf = sC[b * 68 + 16 + jj] + xr_[it * 4 + 1];
            float yg = sC[b * 68 + 32 + jj] + xr_[it * 4 + 2];
            float yo = sC[b * 68 + 48 + jj] + xr_[it * 4 + 3];
            float ig = sigmoidf_(yi);
            float fg = sigmoidf_(yf);
            float gg = tanhf(yg);
            float og = sigmoidf_(yo);
            float craw = fg * ch[it] + ig * gg;
            float hraw = og * tanhf(craw);
            float mt = mr_[it];
            float h2 = hraw * mt;
            float c2 = craw * mt;
            ch[it] = c2;
            float h2r = rnd_tf32(h2);
            hout[b * H_ + j] = h2r;
            outseq[(size_t)t * B_ * 2 * H_ + (size_t)b * 2 * H_ + dir * H_ + j] =
                (out_sel >= 0) ? h2r : h2;
            if (s == T_ - 1) {
                float* hn = dout + (size_t)TB_ * 2 * H_;
                float* cn = hn + (size_t)L_ * B_ * 2 * H_;
                size_t off = (size_t)layer * B_ * 2 * H_ + (size_t)b * 2 * H_ + dir * H_ + j;
                hn[off] = h2;
                cn[off] = c2;
            }
        }

        if (s == T_ - 1) break;

        // prefetch xg + mask for step s+1 (hidden behind barrier wait)
        {
            int tn = dir ? (T_ - 2 - s) : (s + 1);
            const float* xgb = g_xg[dir] + (size_t)tn * B_ * G_;
#pragma unroll
            for (int it = 0; it < 4; it++) {
                const float* base = xgb + (size_t)pb[it] * G_ + pj[it];
                xr_[it * 4 + 0] = __ldg(base);
                xr_[it * 4 + 1] = __ldg(base + H_);
                xr_[it * 4 + 2] = __ldg(base + 2 * H_);
                xr_[it * 4 + 3] = __ldg(base + 3 * H_);
                mr_[it] = __ldg(&masks[tn * B_ + pb[it]]);
            }
        }

        // ---- light per-dir grid barrier (monotonic counter) ----
        __syncthreads();
        if (tid == 0) {
            arrive_release(&g_bar[dir]);
            const int target = NCTA_DIR * (s + 1);
            while (ld_acq(&g_bar[dir]) < target) { }
        }
        __syncthreads();
    }
}

// =====================================================================
// launch
// =====================================================================
extern "C" void kernel_launch(void* const* d_in, const int* in_sizes, int n_in,
                              void* d_out, int out_size)
{
    const float* x      = (const float*)d_in[0];
    const float* masks  = (const float*)d_in[1];
    const float* w_ih_f = (const float*)d_in[2];
    const float* w_hh_f = (const float*)d_in[3];
    const float* b_ih_f = (const float*)d_in[4];
    const float* b_hh_f = (const float*)d_in[5];
    const float* w_ih_b = (const float*)d_in[6];
    const float* w_hh_b = (const float*)d_in[7];
    const float* b_ih_b = (const float*)d_in[8];
    const float* b_hh_b = (const float*)d_in[9];
    float* out = (float*)d_out;

    // idempotent, not a stream op: safe under graph capture
    cudaFuncSetAttribute(lstm_layer_kernel,
                         cudaFuncAttributeMaxDynamicSharedMemorySize, R_SMEM_BYTES);
    cudaFuncSetAttribute(xg_gemm_kernel,
                         cudaFuncAttributeMaxDynamicSharedMemorySize, XG_SMEM_BYTES);

    preround_kernel<<<2048, 256>>>(
        (const float4*)x,
        (const float4*)w_ih_f, (const float4*)w_ih_b,
        (const float4*)b_ih_f, (const float4*)b_hh_f,
        (const float4*)b_ih_b, (const float4*)b_hh_b);

    for (int l = 0; l < L_; l++) {
        int inp_sel = (l == 0) ? -1 : (l - 1);
        int out_sel = (l == L_ - 1) ? -1 : l;

        dim3 gg(G_ / 128, TB_ / 128, 2);
        xg_gemm_kernel<<<gg, 256, XG_SMEM_BYTES>>>(inp_sel, l);

        zero_state_kernel<<<(4 * B_ * H_ + 255) / 256, 256>>>();

        dim3 gs(NCTA_DIR, 1, 2);
        lstm_layer_kernel<<<gs, 256, R_SMEM_BYTES>>>(
            w_hh_f + (size_t)l * G_ * H_, w_hh_b + (size_t)l * G_ * H_,
            masks, out, out_sel, l);
    }
}